// round 3
// baseline (speedup 1.0000x reference)
#include <cuda_runtime.h>
#include <cuda_bf16.h>
#include <cstddef>

// Problem constants (fixed shapes from setup_inputs)
#define T_STEPS 100
#define B_DIM   512
#define I_DIM   512
#define O_DIM   512
#define M_DIM   (T_STEPS * B_DIM)   // 51200
#define BO      (B_DIM * O_DIM)     // 262144

#define BETA_F   0.9f
#define THRESH_F 1.0f

// Scratch for input currents cur[T, B, O] (105 MB) — static device global (no allocs).
__device__ float g_cur[(size_t)T_STEPS * B_DIM * O_DIM];

// ---------------------------------------------------------------------------
// Kernel 1: fp32 NT GEMM  C[m,n] = sum_k A[m,k] * W[n,k] + bias[n]
//   A = x  [M, K] row-major (K contiguous)
//   W      [N, K] row-major (K contiguous)  -> NT GEMM, both K-major
// Tile 128x128x16, 256 threads, 8x8 per-thread micro-tile.
// ---------------------------------------------------------------------------
#define BM 128
#define BN 128
#define BK 16
#define TM 8
#define TN 8

__global__ __launch_bounds__(256)
void snn_gemm_nt_bias(const float* __restrict__ A,
                      const float* __restrict__ W,
                      const float* __restrict__ bias) {
    __shared__ float As[BK][BM + 4];
    __shared__ float Bs[BK][BN + 4];

    const int tid = threadIdx.x;
    const int m0 = blockIdx.y * BM;
    const int n0 = blockIdx.x * BN;

    const int tr = tid / (BN / TN);   // 0..15 : row group
    const int tc = tid % (BN / TN);   // 0..15 : col group

    float acc[TM][TN];
    #pragma unroll
    for (int i = 0; i < TM; ++i)
        #pragma unroll
        for (int j = 0; j < TN; ++j)
            acc[i][j] = 0.0f;

    const int K = I_DIM;

    #pragma unroll 1
    for (int k0 = 0; k0 < K; k0 += BK) {
        // Load A tile (128 x 16) and W tile (128 x 16), transposed into smem.
        // 512 float4 per tile, 256 threads -> 2 float4 each.
        #pragma unroll
        for (int s = 0; s < 2; ++s) {
            const int v   = tid + s * 256;       // 0..511
            const int row = v >> 2;              // 0..127
            const int kc  = (v & 3) << 2;        // 0,4,8,12

            float4 av = *reinterpret_cast<const float4*>(
                &A[(size_t)(m0 + row) * K + k0 + kc]);
            As[kc + 0][row] = av.x;
            As[kc + 1][row] = av.y;
            As[kc + 2][row] = av.z;
            As[kc + 3][row] = av.w;

            float4 wv = *reinterpret_cast<const float4*>(
                &W[(size_t)(n0 + row) * K + k0 + kc]);
            Bs[kc + 0][row] = wv.x;
            Bs[kc + 1][row] = wv.y;
            Bs[kc + 2][row] = wv.z;
            Bs[kc + 3][row] = wv.w;
        }
        __syncthreads();

        #pragma unroll
        for (int kk = 0; kk < BK; ++kk) {
            float ra[TM], rb[TN];
            #pragma unroll
            for (int i = 0; i < TM; ++i) ra[i] = As[kk][tr * TM + i];
            #pragma unroll
            for (int j = 0; j < TN; ++j) rb[j] = Bs[kk][tc * TN + j];
            #pragma unroll
            for (int i = 0; i < TM; ++i)
                #pragma unroll
                for (int j = 0; j < TN; ++j)
                    acc[i][j] += ra[i] * rb[j];
        }
        __syncthreads();
    }

    // Epilogue: add bias (hoisted to registers), write cur.
    float bz[TN];
    #pragma unroll
    for (int j = 0; j < TN; ++j) bz[j] = bias[n0 + tc * TN + j];

    #pragma unroll
    for (int i = 0; i < TM; ++i) {
        const int m = m0 + tr * TM + i;
        #pragma unroll
        for (int j = 0; j < TN; j += 4) {
            const int n = n0 + tc * TN + j;
            float4 o;
            o.x = acc[i][j + 0] + bz[j + 0];
            o.y = acc[i][j + 1] + bz[j + 1];
            o.z = acc[i][j + 2] + bz[j + 2];
            o.w = acc[i][j + 3] + bz[j + 3];
            *reinterpret_cast<float4*>(&g_cur[(size_t)m * O_DIM + n]) = o;
        }
    }
}

// ---------------------------------------------------------------------------
// Kernel 2: leaky integrate-and-fire scan over t, one thread per 4 (b,o)
// lanes, float4-vectorized. Coalesced: consecutive threads hit consecutive o
// within a timestep slab. unroll 5 -> 5 independent loads in flight (MLP).
// ---------------------------------------------------------------------------
__global__ __launch_bounds__(256)
void snn_scan(float* __restrict__ out) {
    const int lane4 = blockIdx.x * blockDim.x + threadIdx.x; // 0 .. BO/4-1
    const size_t base = (size_t)lane4 * 4;

    float4 mem = make_float4(0.f, 0.f, 0.f, 0.f);

    #pragma unroll 5
    for (int t = 0; t < T_STEPS; ++t) {
        const size_t off = (size_t)t * BO + base;
        float4 c = *reinterpret_cast<const float4*>(&g_cur[off]);

        mem.x = BETA_F * mem.x + c.x;
        mem.y = BETA_F * mem.y + c.y;
        mem.z = BETA_F * mem.z + c.z;
        mem.w = BETA_F * mem.w + c.w;

        float4 spk;
        spk.x = (mem.x >= THRESH_F) ? 1.0f : 0.0f;
        spk.y = (mem.y >= THRESH_F) ? 1.0f : 0.0f;
        spk.z = (mem.z >= THRESH_F) ? 1.0f : 0.0f;
        spk.w = (mem.w >= THRESH_F) ? 1.0f : 0.0f;

        *reinterpret_cast<float4*>(&out[off]) = spk;

        mem.x -= spk.x * THRESH_F;
        mem.y -= spk.y * THRESH_F;
        mem.z -= spk.z * THRESH_F;
        mem.w -= spk.w * THRESH_F;
    }
}

// ---------------------------------------------------------------------------
extern "C" void kernel_launch(void* const* d_in, const int* in_sizes, int n_in,
                              void* d_out, int out_size) {
    const float* x    = (const float*)d_in[0]; // [T, B, I]
    const float* w    = (const float*)d_in[1]; // [O, I]
    const float* bias = (const float*)d_in[2]; // [O]
    float* out = (float*)d_out;                // [T, B, O]

    dim3 gemm_grid(O_DIM / BN, M_DIM / BM);    // (4, 400)
    snn_gemm_nt_bias<<<gemm_grid, 256>>>(x, w, bias);

    const int scan_threads = 256;
    const int scan_blocks = (BO / 4) / scan_threads; // 65536/256 = 256
    snn_scan<<<scan_blocks, scan_threads>>>(out);
}